// round 16
// baseline (speedup 1.0000x reference)
#include <cuda_runtime.h>
#include <cuda_bf16.h>
#include <cuda_fp8.h>
#include <cstdint>

#define NB   2
#define NC   512
#define NCQ  64
#define NPIX 4096
#define KTOT 12288   // 3 branches * NPIX

// ---------------- static device scratch (allocation-free) ----------------
__device__ __nv_bfloat16 g_Xt[3][NB][(size_t)NPIX * NC];    // 25 MB
__device__ __nv_bfloat16 g_Wqk[4 * 64 * NC];
__device__ __nv_bfloat16 g_Wv[NC * NC];
__device__ __nv_bfloat16 g_Wl[NC * NC];
__device__ __nv_bfloat16 g_Qt[NB][NPIX * NCQ];
__device__ __nv_bfloat16 g_Kt[3][NB][NPIX * NCQ];
__device__ __nv_bfloat16 g_Vbf[NB][(size_t)NC * NPIX];      //  8 MB
__device__ __nv_bfloat16 g_Et[6][(size_t)NPIX * NPIX];      // 201 MB Et[m][n] (m:K-pixel, n:Q-pixel)
__device__ float g_Zsum[6][NPIX];
__device__ float g_invZ[6][NPIX];
__device__ uint8_t g_Pf8[6][(size_t)NPIX * NPIX];           // 100 MB P = Et * invZ[col], e4m3
__device__ uint8_t g_Vf8[NB][(size_t)NC * NPIX];            //   4 MB V e4m3 (branch-independent)
__device__ __nv_bfloat16 g_attT[NB][(size_t)NPIX * NC];     //   8 MB attT[n][c]

__device__ __forceinline__ uint32_t smem_u32(const void* p) {
    uint32_t a;
    asm("{ .reg .u64 t; cvta.to.shared.u64 t, %1; cvt.u32.u64 %0, t; }" : "=r"(a) : "l"(p));
    return a;
}
__device__ __forceinline__ unsigned short f2fp8x2(float a, float b) {
    return __nv_cvt_float2_to_fp8x2(make_float2(a, b), __NV_SATFINITE, __NV_E4M3);
}

// ===================== weight convert/pack =====================
__global__ __launch_bounds__(256) void convertW_kernel(
    const float* __restrict__ Wq, const float* __restrict__ Wk1,
    const float* __restrict__ Wk2, const float* __restrict__ Wk3,
    const float* __restrict__ Wv, const float* __restrict__ Wl)
{
    const int idx = blockIdx.x * 256 + threadIdx.x;
    if (idx < 131072) {
        const int m = idx >> 9, k = idx & 511;
        const float* W = (m < 64) ? Wq : (m < 128) ? Wk1 : (m < 192) ? Wk2 : Wk3;
        g_Wqk[idx] = __float2bfloat16(W[(m & 63) * NC + k]);
    } else if (idx < 393216) {
        g_Wv[idx - 131072] = __float2bfloat16(Wv[idx - 131072]);
    } else if (idx < 655360) {
        g_Wl[idx - 393216] = __float2bfloat16(Wl[idx - 393216]);
    }
    if (idx < 6 * NPIX) ((float*)g_Zsum)[idx] = 0.f;
}

// ===================== transpose x/y/z -> bf16 [pixel][512] =====================
__global__ __launch_bounds__(256) void transposeX_kernel(
    const float* __restrict__ x, const float* __restrict__ y, const float* __restrict__ z)
{
    const int p = blockIdx.z;
    const int s = p >> 1, b = p & 1;
    const float* in = ((s == 0) ? x : (s == 1) ? y : z) + (size_t)b * NC * NPIX;
    __nv_bfloat16* out = &g_Xt[s][b][0];

    __shared__ float sm[32][33];
    const int p0 = blockIdx.x * 32;
    const int c0 = blockIdx.y * 32;
    const int tx = threadIdx.x, ty = threadIdx.y;
#pragma unroll
    for (int i = 0; i < 4; i++)
        sm[ty + i * 8][tx] = in[(size_t)(c0 + ty + i * 8) * NPIX + p0 + tx];
    __syncthreads();
#pragma unroll
    for (int i = 0; i < 4; i++)
        out[(size_t)(p0 + ty + i * 8) * NC + c0 + tx] = __float2bfloat16(sm[tx][ty + i * 8]);
}

// =====================================================================
// QK projections via HMMA (proven)
// =====================================================================
#define SPA 40

__global__ __launch_bounds__(256, 2) void proj_qk_mma(
    const float* __restrict__ bq, const float* __restrict__ bk1,
    const float* __restrict__ bk2, const float* __restrict__ bk3)
{
    __shared__ __nv_bfloat16 smA[2][64 * SPA];
    __shared__ __nv_bfloat16 smB[2][128 * SPA];

    const int tid = threadIdx.x;
    const int wid = tid >> 5, lane = tid & 31;
    const int mblk = blockIdx.y, b = blockIdx.z;
    const int n0 = blockIdx.x * 128;

    const __nv_bfloat16* __restrict__ Ag = g_Wqk + (size_t)mblk * 64 * NC;
    const int src = (mblk < 2) ? 0 : (mblk - 1);
    const __nv_bfloat16* __restrict__ Bg = &g_Xt[src][b][0];
    const float* bias = (mblk == 0) ? bq : (mblk == 1) ? bk1 : (mblk == 2) ? bk2 : bk3;
    __nv_bfloat16* __restrict__ Out = (mblk == 0) ? &g_Qt[b][0] : &g_Kt[mblk - 1][b][0];

    const int wm = (wid & 1) * 32;
    const int wn = (wid >> 1) * 32;

    float acc[2][4][4];
#pragma unroll
    for (int i = 0; i < 2; i++)
#pragma unroll
        for (int j = 0; j < 4; j++)
#pragma unroll
            for (int q = 0; q < 4; q++) acc[i][j][q] = 0.f;

    const uint32_t sA0 = smem_u32(&smA[0][0]);
    const uint32_t sB0 = smem_u32(&smB[0][0]);
    const int row0 = tid >> 2, cc0 = tid & 3;

    const int la_row = wm + (lane & 15);
    const int la_col = (lane >> 4) << 3;
    const uint32_t a_off = (uint32_t)(la_row * SPA + la_col) * 2;
    const int lb_row = wn + (lane & 7);
    const int lb_col = ((lane >> 3) & 1) << 3;
    const uint32_t b_off = (uint32_t)(lb_row * SPA + lb_col) * 2;

    const int NT = NC / 32;  // 16

    {
        const uint32_t dA = sA0 + (uint32_t)(row0 * SPA + cc0 * 8) * 2;
        const void* srcA = Ag + (size_t)row0 * NC + cc0 * 8;
        asm volatile("cp.async.cg.shared.global [%0], [%1], 16;" :: "r"(dA), "l"(srcA) : "memory");
#pragma unroll
        for (int h = 0; h < 2; h++) {
            const int row = row0 + h * 64;
            const uint32_t dB = sB0 + (uint32_t)(row * SPA + cc0 * 8) * 2;
            const void* srcB = Bg + (size_t)(n0 + row) * NC + cc0 * 8;
            asm volatile("cp.async.cg.shared.global [%0], [%1], 16;" :: "r"(dB), "l"(srcB) : "memory");
        }
        asm volatile("cp.async.commit_group;" ::: "memory");
    }

    for (int kt = 0; kt < NT; ++kt) {
        const int s = kt & 1;
        if (kt + 1 < NT) {
            const int kg = (kt + 1) << 5;
            const uint32_t soA = (uint32_t)((s ^ 1) * 64 * SPA * 2);
            const uint32_t soB = (uint32_t)((s ^ 1) * 128 * SPA * 2);
            const uint32_t dA = sA0 + soA + (uint32_t)(row0 * SPA + cc0 * 8) * 2;
            const void* srcA = Ag + (size_t)row0 * NC + kg + cc0 * 8;
            asm volatile("cp.async.cg.shared.global [%0], [%1], 16;" :: "r"(dA), "l"(srcA) : "memory");
#pragma unroll
            for (int h = 0; h < 2; h++) {
                const int row = row0 + h * 64;
                const uint32_t dB = sB0 + soB + (uint32_t)(row * SPA + cc0 * 8) * 2;
                const void* srcB = Bg + (size_t)(n0 + row) * NC + kg + cc0 * 8;
                asm volatile("cp.async.cg.shared.global [%0], [%1], 16;" :: "r"(dB), "l"(srcB) : "memory");
            }
            asm volatile("cp.async.commit_group;" ::: "memory");
            asm volatile("cp.async.wait_group 1;" ::: "memory");
        } else {
            asm volatile("cp.async.wait_group 0;" ::: "memory");
        }
        __syncthreads();

        const uint32_t stA = sA0 + (uint32_t)(s * 64 * SPA * 2);
        const uint32_t stB = sB0 + (uint32_t)(s * 128 * SPA * 2);
#pragma unroll
        for (int ks = 0; ks < 2; ks++) {
            uint32_t af[2][4];
#pragma unroll
            for (int mt = 0; mt < 2; mt++) {
                const uint32_t addr = stA + a_off + (uint32_t)(ks * 16) * 2 + (uint32_t)(mt * 16 * SPA) * 2;
                asm volatile("ldmatrix.sync.aligned.m8n8.x4.shared.b16 {%0,%1,%2,%3}, [%4];"
                             : "=r"(af[mt][0]), "=r"(af[mt][1]), "=r"(af[mt][2]), "=r"(af[mt][3])
                             : "r"(addr));
            }
            uint32_t bf[4][2];
#pragma unroll
            for (int nt = 0; nt < 4; nt++) {
                const uint32_t addr = stB + b_off + (uint32_t)(ks * 16) * 2 + (uint32_t)(nt * 8 * SPA) * 2;
                asm volatile("ldmatrix.sync.aligned.m8n8.x2.shared.b16 {%0,%1}, [%2];"
                             : "=r"(bf[nt][0]), "=r"(bf[nt][1]) : "r"(addr));
            }
#pragma unroll
            for (int mt = 0; mt < 2; mt++)
#pragma unroll
                for (int nt = 0; nt < 4; nt++) {
                    asm volatile(
                        "mma.sync.aligned.m16n8k16.row.col.f32.bf16.bf16.f32 "
                        "{%0,%1,%2,%3}, {%4,%5,%6,%7}, {%8,%9}, {%0,%1,%2,%3};"
                        : "+f"(acc[mt][nt][0]), "+f"(acc[mt][nt][1]),
                          "+f"(acc[mt][nt][2]), "+f"(acc[mt][nt][3])
                        : "r"(af[mt][0]), "r"(af[mt][1]), "r"(af[mt][2]), "r"(af[mt][3]),
                          "r"(bf[nt][0]), "r"(bf[nt][1]));
                }
        }
        __syncthreads();
    }

    const int erow = lane >> 2;
    const int ecol = (lane & 3) * 2;
#pragma unroll
    for (int mt = 0; mt < 2; mt++) {
        const int c = wm + mt * 16 + erow;
        const float b0 = bias[c], b1 = bias[c + 8];
#pragma unroll
        for (int nt = 0; nt < 4; nt++) {
            const int n = n0 + wn + nt * 8 + ecol;
            Out[(size_t)n * NCQ + c]           = __float2bfloat16(acc[mt][nt][0] + b0);
            Out[(size_t)(n + 1) * NCQ + c]     = __float2bfloat16(acc[mt][nt][1] + b0);
            Out[(size_t)n * NCQ + c + 8]       = __float2bfloat16(acc[mt][nt][2] + b1);
            Out[(size_t)(n + 1) * NCQ + c + 8] = __float2bfloat16(acc[mt][nt][3] + b1);
        }
    }
}

// =====================================================================
// V projection via HMMA (proven)
// =====================================================================
__global__ __launch_bounds__(256, 2) void proj_v_mma(const float* __restrict__ bv)
{
    __shared__ __nv_bfloat16 smA[2][128 * SPA];
    __shared__ __nv_bfloat16 smB[2][128 * SPA];

    const int tid = threadIdx.x;
    const int wid = tid >> 5, lane = tid & 31;
    const int b = blockIdx.z;
    const int m0 = blockIdx.y * 128;
    const int n0 = blockIdx.x * 128;

    const __nv_bfloat16* __restrict__ Ag = g_Wv;
    const __nv_bfloat16* __restrict__ Bg = &g_Xt[0][b][0];

    const int wm = (wid & 1) * 64;
    const int wn = (wid >> 1) * 32;

    float acc[4][4][4];
#pragma unroll
    for (int i = 0; i < 4; i++)
#pragma unroll
        for (int j = 0; j < 4; j++)
#pragma unroll
            for (int q = 0; q < 4; q++) acc[i][j][q] = 0.f;

    const uint32_t sA0 = smem_u32(&smA[0][0]);
    const uint32_t sB0 = smem_u32(&smB[0][0]);
    const int row0 = tid >> 2, cc0 = tid & 3;

    const int la_row = wm + (lane & 15);
    const int la_col = (lane >> 4) << 3;
    const uint32_t a_off = (uint32_t)(la_row * SPA + la_col) * 2;
    const int lb_row = wn + (lane & 7);
    const int lb_col = ((lane >> 3) & 1) << 3;
    const uint32_t b_off = (uint32_t)(lb_row * SPA + lb_col) * 2;

    const int NT = NC / 32;

    {
#pragma unroll
        for (int h = 0; h < 2; h++) {
            const int row = row0 + h * 64;
            const uint32_t dA = sA0 + (uint32_t)(row * SPA + cc0 * 8) * 2;
            const uint32_t dB = sB0 + (uint32_t)(row * SPA + cc0 * 8) * 2;
            const void* srcA = Ag + (size_t)(m0 + row) * NC + cc0 * 8;
            const void* srcB = Bg + (size_t)(n0 + row) * NC + cc0 * 8;
            asm volatile("cp.async.cg.shared.global [%0], [%1], 16;" :: "r"(dA), "l"(srcA) : "memory");
            asm volatile("cp.async.cg.shared.global [%0], [%1], 16;" :: "r"(dB), "l"(srcB) : "memory");
        }
        asm volatile("cp.async.commit_group;" ::: "memory");
    }

    for (int kt = 0; kt < NT; ++kt) {
        const int s = kt & 1;
        if (kt + 1 < NT) {
            const int kg = (kt + 1) << 5;
            const uint32_t stoff = (uint32_t)((s ^ 1) * 128 * SPA * 2);
#pragma unroll
            for (int h = 0; h < 2; h++) {
                const int row = row0 + h * 64;
                const uint32_t dA = sA0 + stoff + (uint32_t)(row * SPA + cc0 * 8) * 2;
                const uint32_t dB = sB0 + stoff + (uint32_t)(row * SPA + cc0 * 8) * 2;
                const void* srcA = Ag + (size_t)(m0 + row) * NC + kg + cc0 * 8;
                const void* srcB = Bg + (size_t)(n0 + row) * NC + kg + cc0 * 8;
                asm volatile("cp.async.cg.shared.global [%0], [%1], 16;" :: "r"(dA), "l"(srcA) : "memory");
                asm volatile("cp.async.cg.shared.global [%0], [%1], 16;" :: "r"(dB), "l"(srcB) : "memory");
            }
            asm volatile("cp.async.commit_group;" ::: "memory");
            asm volatile("cp.async.wait_group 1;" ::: "memory");
        } else {
            asm volatile("cp.async.wait_group 0;" ::: "memory");
        }
        __syncthreads();

        const uint32_t stA = sA0 + (uint32_t)(s * 128 * SPA * 2);
        const uint32_t stB = sB0 + (uint32_t)(s * 128 * SPA * 2);
#pragma unroll
        for (int ks = 0; ks < 2; ks++) {
            uint32_t af[4][4];
#pragma unroll
            for (int mt = 0; mt < 4; mt++) {
                const uint32_t addr = stA + a_off + (uint32_t)(ks * 16) * 2 + (uint32_t)(mt * 16 * SPA) * 2;
                asm volatile("ldmatrix.sync.aligned.m8n8.x4.shared.b16 {%0,%1,%2,%3}, [%4];"
                             : "=r"(af[mt][0]), "=r"(af[mt][1]), "=r"(af[mt][2]), "=r"(af[mt][3])
                             : "r"(addr));
            }
            uint32_t bf[4][2];
#pragma unroll
            for (int nt = 0; nt < 4; nt++) {
                const uint32_t addr = stB + b_off + (uint32_t)(ks * 16) * 2 + (uint32_t)(nt * 8 * SPA) * 2;
                asm volatile("ldmatrix.sync.aligned.m8n8.x2.shared.b16 {%0,%1}, [%2];"
                             : "=r"(bf[nt][0]), "=r"(bf[nt][1]) : "r"(addr));
            }
#pragma unroll
            for (int mt = 0; mt < 4; mt++)
#pragma unroll
                for (int nt = 0; nt < 4; nt++) {
                    asm volatile(
                        "mma.sync.aligned.m16n8k16.row.col.f32.bf16.bf16.f32 "
                        "{%0,%1,%2,%3}, {%4,%5,%6,%7}, {%8,%9}, {%0,%1,%2,%3};"
                        : "+f"(acc[mt][nt][0]), "+f"(acc[mt][nt][1]),
                          "+f"(acc[mt][nt][2]), "+f"(acc[mt][nt][3])
                        : "r"(af[mt][0]), "r"(af[mt][1]), "r"(af[mt][2]), "r"(af[mt][3]),
                          "r"(bf[nt][0]), "r"(bf[nt][1]));
                }
        }
        __syncthreads();
    }

    __nv_bfloat16* __restrict__ V = &g_Vbf[b][0];
    const int erow = lane >> 2;
    const int ecol = (lane & 3) * 2;
#pragma unroll
    for (int mt = 0; mt < 4; mt++) {
        const int c = m0 + wm + mt * 16 + erow;
        const float b0 = bv[c], b1 = bv[c + 8];
#pragma unroll
        for (int nt = 0; nt < 4; nt++) {
            const int n = n0 + wn + nt * 8 + ecol;
            *(__nv_bfloat162*)(V + (size_t)c * NPIX + n) =
                __floats2bfloat162_rn(acc[mt][nt][0] + b0, acc[mt][nt][1] + b0);
            *(__nv_bfloat162*)(V + (size_t)(c + 8) * NPIX + n) =
                __floats2bfloat162_rn(acc[mt][nt][2] + b1, acc[mt][nt][3] + b1);
        }
    }
}

// =====================================================================
// Scores via HMMA + fused column-sum, SMEM-staged coalesced Et store (proven)
// =====================================================================
#define SCB 72
#define STG 136

__global__ __launch_bounds__(256, 2) void scores_mma_kernel()
{
    __shared__ __nv_bfloat16 sm_buf[2 * 128 * SCB];
    __shared__ float cs[128];

    const int tid = threadIdx.x;
    const int wid = tid >> 5, lane = tid & 31;
    const int zz = blockIdx.z;
    const int b = zz & 1, br = zz >> 1;
    const int m0 = blockIdx.y * 128;
    const int n0 = blockIdx.x * 128;

    const __nv_bfloat16* __restrict__ Ag = &g_Kt[br][b][0];
    const __nv_bfloat16* __restrict__ Bg = &g_Qt[b][0];

    const int wm = (wid & 1) * 64;
    const int wn = (wid >> 1) * 32;

    float acc[4][4][4];
#pragma unroll
    for (int i = 0; i < 4; i++)
#pragma unroll
        for (int j = 0; j < 4; j++)
#pragma unroll
            for (int q = 0; q < 4; q++) acc[i][j][q] = 0.f;

    const uint32_t sA0 = smem_u32(&sm_buf[0]);
    const uint32_t sB0 = smem_u32(&sm_buf[128 * SCB]);

#pragma unroll
    for (int c = 0; c < 4; c++) {
        const int idx = c * 256 + tid;
        const int row = idx >> 3, cc = idx & 7;
        const uint32_t dA = sA0 + (uint32_t)(row * SCB + cc * 8) * 2;
        const uint32_t dB = sB0 + (uint32_t)(row * SCB + cc * 8) * 2;
        const void* srcA = Ag + (size_t)(m0 + row) * NCQ + cc * 8;
        const void* srcB = Bg + (size_t)(n0 + row) * NCQ + cc * 8;
        asm volatile("cp.async.cg.shared.global [%0], [%1], 16;" :: "r"(dA), "l"(srcA) : "memory");
        asm volatile("cp.async.cg.shared.global [%0], [%1], 16;" :: "r"(dB), "l"(srcB) : "memory");
    }
    asm volatile("cp.async.commit_group;" ::: "memory");
    if (tid < 128) cs[tid] = 0.f;
    asm volatile("cp.async.wait_group 0;" ::: "memory");
    __syncthreads();

    const int la_row = wm + (lane & 15);
    const int la_col = (lane >> 4) << 3;
    const uint32_t a_off = sA0 + (uint32_t)(la_row * SCB + la_col) * 2;
    const int lb_row = wn + (lane & 7);
    const int lb_col = ((lane >> 3) & 1) << 3;
    const uint32_t b_off = sB0 + (uint32_t)(lb_row * SCB + lb_col) * 2;

#pragma unroll
    for (int ks = 0; ks < 4; ks++) {
        uint32_t af[4][4];
#pragma unroll
        for (int mt = 0; mt < 4; mt++) {
            const uint32_t addr = a_off + (uint32_t)(ks * 16) * 2 + (uint32_t)(mt * 16 * SCB) * 2;
            asm volatile("ldmatrix.sync.aligned.m8n8.x4.shared.b16 {%0,%1,%2,%3}, [%4];"
                         : "=r"(af[mt][0]), "=r"(af[mt][1]), "=r"(af[mt][2]), "=r"(af[mt][3])
                         : "r"(addr));
        }
        uint32_t bf[4][2];
#pragma unroll
        for (int nt = 0; nt < 4; nt++) {
            const uint32_t addr = b_off + (uint32_t)(ks * 16) * 2 + (uint32_t)(nt * 8 * SCB) * 2;
            asm volatile("ldmatrix.sync.aligned.m8n8.x2.shared.b16 {%0,%1}, [%2];"
                         : "=r"(bf[nt][0]), "=r"(bf[nt][1]) : "r"(addr));
        }
#pragma unroll
        for (int mt = 0; mt < 4; mt++)
#pragma unroll
            for (int nt = 0; nt < 4; nt++) {
                asm volatile(
                    "mma.sync.aligned.m16n8k16.row.col.f32.bf16.bf16.f32 "
                    "{%0,%1,%2,%3}, {%4,%5,%6,%7}, {%8,%9}, {%0,%1,%2,%3};"
                    : "+f"(acc[mt][nt][0]), "+f"(acc[mt][nt][1]),
                      "+f"(acc[mt][nt][2]), "+f"(acc[mt][nt][3])
                    : "r"(af[mt][0]), "r"(af[mt][1]), "r"(af[mt][2]), "r"(af[mt][3]),
                      "r"(bf[nt][0]), "r"(bf[nt][1]));
            }
    }
    __syncthreads();

    __nv_bfloat16* stage = &sm_buf[0];
    const int erow = lane >> 2;
    const int ecol = (lane & 3) * 2;
#pragma unroll
    for (int nt = 0; nt < 4; nt++) {
        const int cl = wn + nt * 8 + ecol;
        float s0 = 0.f, s1 = 0.f;
#pragma unroll
        for (int mt = 0; mt < 4; mt++) {
            const int rl = wm + mt * 16 + erow;
            float e0 = __expf(acc[mt][nt][0]);
            float e1 = __expf(acc[mt][nt][1]);
            float e2 = __expf(acc[mt][nt][2]);
            float e3 = __expf(acc[mt][nt][3]);
            *(__nv_bfloat162*)(stage + rl * STG + cl)       = __floats2bfloat162_rn(e0, e1);
            *(__nv_bfloat162*)(stage + (rl + 8) * STG + cl) = __floats2bfloat162_rn(e2, e3);
            s0 += e0 + e2;
            s1 += e1 + e3;
        }
        atomicAdd(&cs[cl], s0);
        atomicAdd(&cs[cl + 1], s1);
    }
    __syncthreads();

    __nv_bfloat16* __restrict__ E = &g_Et[zz][0];
#pragma unroll
    for (int c = 0; c < 8; c++) {
        const int id = c * 256 + tid;
        const int row = id >> 4, c16 = id & 15;
        *(uint4*)(E + (size_t)(m0 + row) * NPIX + n0 + c16 * 8) =
            *(const uint4*)(stage + row * STG + c16 * 8);
    }
    if (tid < 128) atomicAdd(&g_Zsum[zz][n0 + tid], cs[tid]);
}

// ===================== invert Z =====================
__global__ __launch_bounds__(1024) void invertZ_kernel()
{
    const int zz = blockIdx.x;
#pragma unroll
    for (int k = 0; k < 4; k++) {
        const int i = threadIdx.x + k * 1024;
        g_invZ[zz][i] = 1.0f / g_Zsum[zz][i];
    }
}

// ===================== P = e4m3(Et * invZ[col]) — grid (4096, 6) =====================
__global__ __launch_bounds__(256) void convertE_kernel()
{
    const int zz = blockIdx.y;
    const size_t base = (size_t)blockIdx.x * 4096 + threadIdx.x * 16;
    const int col = (int)(base & 4095);
    const __nv_bfloat16* Ep = &g_Et[zz][0] + base;
    const float* iz = &g_invZ[zz][0] + col;

    union { __nv_bfloat162 h2[8]; uint4 v[2]; } e;
    e.v[0] = *(const uint4*)Ep;
    e.v[1] = *(const uint4*)(Ep + 8);
    float z[16];
#pragma unroll
    for (int q = 0; q < 4; q++) *(float4*)&z[q * 4] = *(const float4*)(iz + q * 4);

    union { unsigned short s[8]; uint4 v; } o;
#pragma unroll
    for (int p = 0; p < 8; p++) {
        float a = __bfloat162float(e.h2[p].x) * z[2 * p];
        float bb = __bfloat162float(e.h2[p].y) * z[2 * p + 1];
        o.s[p] = f2fp8x2(a, bb);
    }
    *(uint4*)(&g_Pf8[zz][0] + base) = o.v;
}

// ===================== Vf8 = e4m3(Vbf) — grid (512, NB) =====================
__global__ __launch_bounds__(256) void convertVf8_kernel()
{
    const int b = blockIdx.y;
    const size_t base = (size_t)blockIdx.x * 4096 + threadIdx.x * 16;
    const __nv_bfloat16* Vp = &g_Vbf[b][0] + base;
    union { __nv_bfloat162 h2[8]; uint4 v[2]; } e;
    e.v[0] = *(const uint4*)Vp;
    e.v[1] = *(const uint4*)(Vp + 8);
    union { unsigned short s[8]; uint4 v; } o;
#pragma unroll
    for (int p = 0; p < 8; p++)
        o.s[p] = f2fp8x2(__bfloat162float(e.h2[p].x), __bfloat162float(e.h2[p].y));
    *(uint4*)(&g_Vf8[b][0] + base) = o.v;
}

// =====================================================================
// Aggregation GEMM in FP8 (QMMA m16n8k32 e4m3):
//   attT[n][c] = sum_m Vf8[c][m] * Pf8[z][n][m]   (m over 3*4096)
// BK=64 fp8 (64B/row, pitch 80B conflict-free), double buffer, tiles as R9.
// grid (32, 4, NB), 256 threads, 40KB static SMEM.
// =====================================================================
#define SAF 80   // bytes per smem row

__global__ __launch_bounds__(256, 2) void attn_mma_kernel()
{
    __shared__ uint8_t smA[2][128 * SAF];
    __shared__ uint8_t smB[2][128 * SAF];

    const int tid = threadIdx.x;
    const int wid = tid >> 5, lane = tid & 31;
    const int b = blockIdx.z;
    const int m0 = blockIdx.y * 128;   // channel block
    const int n0 = blockIdx.x * 128;   // pixel block

    const uint8_t* __restrict__ Ag = &g_Vf8[b][0];

    const int wm = (wid & 1) * 64;
    const int wn = (wid >> 1) * 32;

    float acc[4][4][4];
#pragma unroll
    for (int i = 0; i < 4; i++)
#pragma unroll
        for (int j = 0; j < 4; j++)
#pragma unroll
            for (int q = 0; q < 4; q++) acc[i][j][q] = 0.f;

    const uint32_t sA0 = smem_u32(&smA[0][0]);
    const uint32_t sB0 = smem_u32(&smB[0][0]);

    const int row0 = tid >> 2;     // 0..63
    const int cc0  = tid & 3;      // 16B chunk within 64B row

    // ldmatrix offsets: "b16 units" = 2 fp8 bytes; same fragment mapping as bf16 k16
    const int la_row = wm + (lane & 15);
    const int la_col = (lane >> 4) << 3;
    const uint32_t a_off = (uint32_t)(la_row * SAF + la_col * 2);
    const int lb_row = wn + (lane & 7);
    const int lb_col = ((lane >> 3) & 1) << 3;
    const uint32_t b_off = (uint32_t)(lb_row * SAF + lb_col * 2);

    const int NT = KTOT / 64;  // 192

    {
        const uint8_t* Bg = &g_Pf8[b][0];
#pragma unroll
        for (int h = 0; h < 2; h++) {
            const int row = row0 + h * 64;
            const uint32_t dA = sA0 + (uint32_t)(row * SAF + cc0 * 16);
            const uint32_t dB = sB0 + (uint32_t)(row * SAF + cc0 * 16);
            const void* srcA = Ag + (size_t)(m0 + row) * NPIX + cc0 * 16;
            const void* srcB = Bg + (size_t)(n0 + row) * NPIX + cc0 * 16;
            asm volatile("cp.async.cg.shared.global [%0], [%1], 16;" :: "r"(dA), "l"(srcA) : "memory");
            asm volatile("cp.async.cg.shared.global [%0], [%1], 16;" :: "r"(dB), "l"(srcB) : "memory");
        }
        asm volatile("cp.async.commit_group;" ::: "memory");
    }

    for (int kt = 0; kt < NT; ++kt) {
        const int s = kt & 1;
        if (kt + 1 < NT) {
            const int kg = (kt + 1) << 6;
            const int br = kg >> 12;
            const int kloc = kg & 4095;
            const uint8_t* __restrict__ Bg = &g_Pf8[br * 2 + b][0];
            const uint32_t stoff = (uint32_t)((s ^ 1) * 128 * SAF);
#pragma unroll
            for (int h = 0; h < 2; h++) {
                const int row = row0 + h * 64;
                const uint32_t dA = sA0 + stoff + (uint32_t)(row * SAF + cc0 * 16);
                const uint32_t dB = sB0 + stoff + (uint32_t)(row * SAF + cc0 * 16);
                const void* srcA = Ag + (size_t)(m0 + row) * NPIX + kloc + cc0 * 16;
                const void* srcB = Bg + (size_t)(n0 + row) * NPIX + kloc + cc0 * 16;
                asm volatile("cp.async.cg.shared.global [%0], [%1], 16;" :: "r"(dA), "l"(srcA) : "memory");
                asm volatile("cp.async.cg.shared.global [%0], [%1], 16;" :: "r"(dB), "l"(srcB) : "memory");
            }
            asm volatile("cp.async.commit_group;" ::: "memory");
            asm volatile("cp.async.wait_group 1;" ::: "memory");
        } else {
            asm volatile("cp.async.wait_group 0;" ::: "memory");
        }
        __syncthreads();

        const uint32_t stA = sA0 + (uint32_t)(s * 128 * SAF);
        const uint32_t stB = sB0 + (uint32_t)(s * 128 * SAF);

#pragma unroll
        for (int ks = 0; ks < 2; ks++) {   // two k32 steps cover 64 fp8
            uint32_t af[4][4];
#pragma unroll
            for (int mt = 0; mt < 4; mt++) {
                const uint32_t addr = stA + a_off + (uint32_t)(ks * 32) + (uint32_t)(mt * 16 * SAF);
                asm volatile("ldmatrix.sync.aligned.m8n8.x4.shared.b16 {%0,%1,%2,%3}, [%4];"
                             : "=r"(af[mt][0]), "=r"(af[mt][1]), "=r"(af[mt][2]), "=r"(af[mt][3])
                             : "r"(addr));
            }
            uint32_t bf[4][2];
#pragma unroll
            for (int nt = 0; nt < 4; nt++) {
                const uint32_t addr = stB + b_off + (uint32_t)(ks * 32) + (uint32_t)(nt * 8 * SAF);
                asm volatile("ldmatrix.sync.aligned.m8n8.x2.shared.b16 {%0,%1}, [%2];"
                             : "=r"(bf[nt][0]), "=r"(bf[nt][1]) : "r"(addr));
            }
#pragma unroll
            for (int mt = 0; mt < 4; mt++)
#pragma unroll
                for (int nt = 0; nt < 4; nt++) {
                    asm volatile(
                        "mma.sync.aligned.m16n8k32.row.col.f32.e4m3.e4m3.f32 "
                        "{%0,%1,%2,%3}, {%4,%5,%6,%7}, {%8,%9}, {%0,%1,%2,%3};"
                        : "+f"(acc[mt][nt][0]), "+f"(acc[mt][nt][1]),
                          "+f"(acc[mt][nt][2]), "+f"(acc[mt][nt][3])
                        : "r"(af[mt][0]), "r"(af[mt][1]), "r"(af[mt][2]), "r"(af[mt][3]),
                          "r"(bf[nt][0]), "r"(bf[nt][1]));
                }
        }
        __syncthreads();
    }

    __nv_bfloat16* __restrict__ at = &g_attT[b][0];
    const int erow = lane >> 2;
    const int ecol = (lane & 3) * 2;
#pragma unroll
    for (int mt = 0; mt < 4; mt++) {
#pragma unroll
        for (int nt = 0; nt < 4; nt++) {
            const int m = m0 + wm + mt * 16 + erow;
            const int n = n0 + wn + nt * 8 + ecol;
            at[(size_t)n * NC + m]           = __float2bfloat16(acc[mt][nt][0]);
            at[(size_t)(n + 1) * NC + m]     = __float2bfloat16(acc[mt][nt][1]);
            at[(size_t)n * NC + m + 8]       = __float2bfloat16(acc[mt][nt][2]);
            at[(size_t)(n + 1) * NC + m + 8] = __float2bfloat16(acc[mt][nt][3]);
        }
    }
}

// =====================================================================
// Final via HMMA (proven)
// =====================================================================
__global__ __launch_bounds__(256, 2) void final_mma(
    const float* __restrict__ bl, const float* __restrict__ xin,
    const float* __restrict__ gamma, float* __restrict__ out)
{
    __shared__ __nv_bfloat16 smA[2][128 * SPA];
    __shared__ __nv_bfloat16 smB[2][128 * SPA];

    const int tid = threadIdx.x;
    const int wid = tid >> 5, lane = tid & 31;
    const int b = blockIdx.z;
    const int m0 = blockIdx.y * 128;
    const int n0 = blockIdx.x * 128;

    const __nv_bfloat16* __restrict__ Ag = g_Wl;
    const __nv_bfloat16* __restrict__ Bg = &g_attT[b][0];

    const int wm = (wid & 1) * 64;
    const int wn = (wid >> 1) * 32;

    float acc[4][4][4];
#pragma unroll
    for (int i = 0; i < 4; i++)
#pragma unroll
        for (int j = 0; j < 4; j++)
#pragma unroll
            for (int q = 0; q < 4; q++) acc[i][j][q] = 0.f;

    const uint32_t sA0 = smem_u32(&smA[0][0]);
    const uint32_t sB0 = smem_u32(&smB[0][0]);
    const int row0 = tid >> 2, cc0 = tid & 3;

    const int la_row = wm + (lane & 15);
    const int la_col = (lane >> 4) << 3;
    const uint32_t a_off = (uint32_t)(la_row * SPA + la_col) * 2;
    const int lb_row = wn + (lane & 7);
    const int lb_col = ((lane >> 3) & 1) << 3;
    const uint32_t b_off = (uint32_t)(lb_row * SPA + lb_col) * 2;

    const int NT = NC / 32;

    {
#pragma unroll
        for (int h = 0; h < 2; h++) {
            const int row = row0 + h * 64;
            const uint32_t dA = sA0 + (uint32_t)(row * SPA + cc0 * 8) * 2;
            const uint32_t dB = sB0 + (uint32_t)(row * SPA + cc0 * 8) * 2;
            const void* srcA = Ag + (size_t)(m0 + row) * NC + cc0 * 8;
            const void* srcB = Bg + (size_t)(n0 + row) * NC + cc0 * 8;
            asm volatile("cp.async.cg.shared.global [%0], [%1], 16;" :: "r"(dA), "l"(srcA) : "memory");
            asm volatile("cp.async.cg.shared.global [%0], [%1], 16;" :: "r"(dB), "l"(srcB) : "memory");
        }
        asm volatile("cp.async.commit_group;" ::: "memory");
    }

    for (int kt = 0; kt < NT; ++kt) {
        const int s = kt & 1;
        if (kt + 1 < NT) {
            const int kg = (kt + 1) << 5;
            const uint32_t stoff = (uint32_t)((s ^ 1) * 128 * SPA * 2);
#pragma unroll
            for (int h = 0; h < 2; h++) {
                const int row = row0 + h * 64;
                const uint32_t dA = sA0 + stoff + (uint32_t)(row * SPA + cc0 * 8) * 2;
                const uint32_t dB = sB0 + stoff + (uint32_t)(row * SPA + cc0 * 8) * 2;
                const void* srcA = Ag + (size_t)(m0 + row) * NC + kg + cc0 * 8;
                const void* srcB = Bg + (size_t)(n0 + row) * NC + kg + cc0 * 8;
                asm volatile("cp.async.cg.shared.global [%0], [%1], 16;" :: "r"(dA), "l"(srcA) : "memory");
                asm volatile("cp.async.cg.shared.global [%0], [%1], 16;" :: "r"(dB), "l"(srcB) : "memory");
            }
            asm volatile("cp.async.commit_group;" ::: "memory");
            asm volatile("cp.async.wait_group 1;" ::: "memory");
        } else {
            asm volatile("cp.async.wait_group 0;" ::: "memory");
        }
        __syncthreads();

        const uint32_t stA = sA0 + (uint32_t)(s * 128 * SPA * 2);
        const uint32_t stB = sB0 + (uint32_t)(s * 128 * SPA * 2);
#pragma unroll
        for (int ks = 0; ks < 2; ks++) {
            uint32_t af[4][4];
#pragma unroll
            for (int mt = 0; mt < 4; mt++) {
                const uint32_t addr = stA + a_off + (uint32_t)(ks * 16) * 2 + (uint32_t)(mt * 16 * SPA) * 2;
                asm volatile("ldmatrix.sync.aligned.m8n8.x4.shared.b16 {%0,%1,%2,%3}, [%4];"
                             : "=r"(af[mt][0]), "=r"(af[mt][1]), "=r"(af[mt][2]), "=r"(af[mt][3])
                             : "r"(addr));
            }
            uint32_t bf[4][2];
#pragma unroll
            for (int nt = 0; nt < 4; nt++) {
                const uint32_t addr = stB + b_off + (uint32_t)(ks * 16) * 2 + (uint32_t)(nt * 8 * SPA) * 2;
                asm volatile("ldmatrix.sync.aligned.m8n8.x2.shared.b16 {%0,%1}, [%2];"
                             : "=r"(bf[nt][0]), "=r"(bf[nt][1]) : "r"(addr));
            }
#pragma unroll
            for (int mt = 0; mt < 4; mt++)
#pragma unroll
                for (int nt = 0; nt < 4; nt++) {
                    asm volatile(
                        "mma.sync.aligned.m16n8k16.row.col.f32.bf16.bf16.f32 "
                        "{%0,%1,%2,%3}, {%4,%5,%6,%7}, {%8,%9}, {%0,%1,%2,%3};"
                        : "+f"(acc[mt][nt][0]), "+f"(acc[mt][nt][1]),
                          "+f"(acc[mt][nt][2]), "+f"(acc[mt][nt][3])
                        : "r"(af[mt][0]), "r"(af[mt][1]), "r"(af[mt][2]), "r"(af[mt][3]),
                          "r"(bf[nt][0]), "r"(bf[nt][1]));
                }
        }
        __syncthreads();
    }

    const float g = gamma[0];
    const int erow = lane >> 2;
    const int ecol = (lane & 3) * 2;
#pragma unroll
    for (int mt = 0; mt < 4; mt++) {
        const int c = m0 + wm + mt * 16 + erow;
        const float b0 = bl[c], b1 = bl[c + 8];
#pragma unroll
        for (int nt = 0; nt < 4; nt++) {
            const int n = n0 + wn + nt * 8 + ecol;
            const size_t base0 = (size_t)b * NC * NPIX + (size_t)c * NPIX + n;
            const size_t base1 = (size_t)b * NC * NPIX + (size_t)(c + 8) * NPIX + n;
            float2 x0 = *(const float2*)(xin + base0);
            float2 x1 = *(const float2*)(xin + base1);
            *(float2*)(out + base0) = make_float2(x0.x + g * (acc[mt][nt][0] + b0),
                                                  x0.y + g * (acc[mt][nt][1] + b0));
            *(float2*)(out + base1) = make_float2(x1.x + g * (acc[mt][nt][2] + b1),
                                                  x1.y + g * (acc[mt][nt][3] + b1));
        }
    }
}

// =====================================================================
extern "C" void kernel_launch(void* const* d_in, const int* in_sizes, int n_in,
                              void* d_out, int out_size)
{
    const float* x   = (const float*)d_in[0];
    const float* y   = (const float*)d_in[1];
    const float* zz  = (const float*)d_in[2];
    const float* Wq  = (const float*)d_in[3];
    const float* bq  = (const float*)d_in[4];
    const float* Wk1 = (const float*)d_in[5];
    const float* bk1 = (const float*)d_in[6];
    const float* Wk2 = (const float*)d_in[7];
    const float* bk2 = (const float*)d_in[8];
    const float* Wk3 = (const float*)d_in[9];
    const float* bk3 = (const float*)d_in[10];
    const float* Wv  = (const float*)d_in[11];
    const float* bv  = (const float*)d_in[12];
    const float* Wl  = (const float*)d_in[13];
    const float* bl  = (const float*)d_in[14];
    const float* gm  = (const float*)d_in[15];
    float* out = (float*)d_out;

    dim3 blk(256);
    convertW_kernel<<<2560, blk>>>(Wq, Wk1, Wk2, Wk3, Wv, Wl);
    transposeX_kernel<<<dim3(128, 16, 6), dim3(32, 8)>>>(x, y, zz);
    proj_qk_mma<<<dim3(32, 4, NB), blk>>>(bq, bk1, bk2, bk3);
    proj_v_mma <<<dim3(32, 4, NB), blk>>>(bv);
    scores_mma_kernel<<<dim3(32, 32, 6), blk>>>();
    invertZ_kernel<<<6, 1024>>>();
    convertE_kernel<<<dim3(4096, 6), blk>>>();
    convertVf8_kernel<<<dim3(512, NB), blk>>>();
    attn_mma_kernel<<<dim3(32, 4, NB), blk>>>();
    final_mma<<<dim3(32, 4, NB), blk>>>(bl, x, gm, out);
}

// round 17
// speedup vs baseline: 1.0331x; 1.0331x over previous
#include <cuda_runtime.h>
#include <cuda_bf16.h>
#include <cstdint>

#define NB   2
#define NC   512
#define NCQ  64
#define NPIX 4096
#define KTOT 12288   // 3 branches * NPIX

// ---------------- static device scratch (allocation-free) ----------------
__device__ __nv_bfloat16 g_Xt[3][NB][(size_t)NPIX * NC];    // 25 MB  Xt[s][b][pixel][ch]
__device__ __nv_bfloat16 g_Wqk[4 * 64 * NC];                // 256KB  [Wq;Wk1;Wk2;Wk3]
__device__ __nv_bfloat16 g_Wv[NC * NC];                     // 512KB
__device__ __nv_bfloat16 g_Wl[NC * NC];                     // 512KB
__device__ __nv_bfloat16 g_Qt[NB][NPIX * NCQ];              //  1 MB  Qt[i][c]
__device__ __nv_bfloat16 g_Kt[3][NB][NPIX * NCQ];           //  3 MB  Kt[j][c]
__device__ __nv_bfloat16 g_Vbf[NB][(size_t)NC * NPIX];      //  8 MB  V[c][i] bf16
__device__ __nv_bfloat16 g_Et[6][(size_t)NPIX * NPIX];      // 201 MB Et[z][j][i]=exp(S[i][j])
__device__ float g_Zsum[6][NPIX];
__device__ float g_invZ[6][NPIX];
__device__ __nv_bfloat16 g_Abf[NB][(size_t)NC * KTOT];      //  25 MB A[c][br*4096+k] = V*invZ
__device__ __nv_bfloat16 g_attT[NB][(size_t)NPIX * NC];     //  8 MB  attT[n][c]

__device__ __forceinline__ uint32_t smem_u32(const void* p) {
    uint32_t a;
    asm("{ .reg .u64 t; cvta.to.shared.u64 t, %1; cvt.u32.u64 %0, t; }" : "=r"(a) : "l"(p));
    return a;
}

// ===================== weight convert/pack + Zsum zero =====================
__global__ __launch_bounds__(256) void convertW_kernel(
    const float* __restrict__ Wq, const float* __restrict__ Wk1,
    const float* __restrict__ Wk2, const float* __restrict__ Wk3,
    const float* __restrict__ Wv, const float* __restrict__ Wl)
{
    const int idx = blockIdx.x * 256 + threadIdx.x;
    if (idx < 131072) {
        const int m = idx >> 9, k = idx & 511;
        const float* W = (m < 64) ? Wq : (m < 128) ? Wk1 : (m < 192) ? Wk2 : Wk3;
        g_Wqk[idx] = __float2bfloat16(W[(m & 63) * NC + k]);
    } else if (idx < 393216) {
        g_Wv[idx - 131072] = __float2bfloat16(Wv[idx - 131072]);
    } else if (idx < 655360) {
        g_Wl[idx - 393216] = __float2bfloat16(Wl[idx - 393216]);
    }
    if (idx < 6 * NPIX) ((float*)g_Zsum)[idx] = 0.f;
}

// ===================== transpose x/y/z -> bf16 [pixel][512] =====================
__global__ __launch_bounds__(256) void transposeX_kernel(
    const float* __restrict__ x, const float* __restrict__ y, const float* __restrict__ z)
{
    const int p = blockIdx.z;
    const int s = p >> 1, b = p & 1;
    const float* in = ((s == 0) ? x : (s == 1) ? y : z) + (size_t)b * NC * NPIX;
    __nv_bfloat16* out = &g_Xt[s][b][0];

    __shared__ float sm[32][33];
    const int p0 = blockIdx.x * 32;
    const int c0 = blockIdx.y * 32;
    const int tx = threadIdx.x, ty = threadIdx.y;
#pragma unroll
    for (int i = 0; i < 4; i++)
        sm[ty + i * 8][tx] = in[(size_t)(c0 + ty + i * 8) * NPIX + p0 + tx];
    __syncthreads();
#pragma unroll
    for (int i = 0; i < 4; i++)
        out[(size_t)(p0 + ty + i * 8) * NC + c0 + tx] = __float2bfloat16(sm[tx][ty + i * 8]);
}

// =====================================================================
// QK projections via HMMA, write Qt/Kt bf16 transposed directly.
// =====================================================================
#define SPA 40

__global__ __launch_bounds__(256, 2) void proj_qk_mma(
    const float* __restrict__ bq, const float* __restrict__ bk1,
    const float* __restrict__ bk2, const float* __restrict__ bk3)
{
    __shared__ __nv_bfloat16 smA[2][64 * SPA];
    __shared__ __nv_bfloat16 smB[2][128 * SPA];

    const int tid = threadIdx.x;
    const int wid = tid >> 5, lane = tid & 31;
    const int mblk = blockIdx.y, b = blockIdx.z;
    const int n0 = blockIdx.x * 128;

    const __nv_bfloat16* __restrict__ Ag = g_Wqk + (size_t)mblk * 64 * NC;
    const int src = (mblk < 2) ? 0 : (mblk - 1);
    const __nv_bfloat16* __restrict__ Bg = &g_Xt[src][b][0];
    const float* bias = (mblk == 0) ? bq : (mblk == 1) ? bk1 : (mblk == 2) ? bk2 : bk3;
    __nv_bfloat16* __restrict__ Out = (mblk == 0) ? &g_Qt[b][0] : &g_Kt[mblk - 1][b][0];

    const int wm = (wid & 1) * 32;
    const int wn = (wid >> 1) * 32;

    float acc[2][4][4];
#pragma unroll
    for (int i = 0; i < 2; i++)
#pragma unroll
        for (int j = 0; j < 4; j++)
#pragma unroll
            for (int q = 0; q < 4; q++) acc[i][j][q] = 0.f;

    const uint32_t sA0 = smem_u32(&smA[0][0]);
    const uint32_t sB0 = smem_u32(&smB[0][0]);
    const int row0 = tid >> 2, cc0 = tid & 3;

    const int la_row = wm + (lane & 15);
    const int la_col = (lane >> 4) << 3;
    const uint32_t a_off = (uint32_t)(la_row * SPA + la_col) * 2;
    const int lb_row = wn + (lane & 7);
    const int lb_col = ((lane >> 3) & 1) << 3;
    const uint32_t b_off = (uint32_t)(lb_row * SPA + lb_col) * 2;

    const int NT = NC / 32;  // 16

    {
        const uint32_t dA = sA0 + (uint32_t)(row0 * SPA + cc0 * 8) * 2;
        const void* srcA = Ag + (size_t)row0 * NC + cc0 * 8;
        asm volatile("cp.async.cg.shared.global [%0], [%1], 16;" :: "r"(dA), "l"(srcA) : "memory");
#pragma unroll
        for (int h = 0; h < 2; h++) {
            const int row = row0 + h * 64;
            const uint32_t dB = sB0 + (uint32_t)(row * SPA + cc0 * 8) * 2;
            const void* srcB = Bg + (size_t)(n0 + row) * NC + cc0 * 8;
            asm volatile("cp.async.cg.shared.global [%0], [%1], 16;" :: "r"(dB), "l"(srcB) : "memory");
        }
        asm volatile("cp.async.commit_group;" ::: "memory");
    }

    for (int kt = 0; kt < NT; ++kt) {
        const int s = kt & 1;
        if (kt + 1 < NT) {
            const int kg = (kt + 1) << 5;
            const uint32_t soA = (uint32_t)((s ^ 1) * 64 * SPA * 2);
            const uint32_t soB = (uint32_t)((s ^ 1) * 128 * SPA * 2);
            const uint32_t dA = sA0 + soA + (uint32_t)(row0 * SPA + cc0 * 8) * 2;
            const void* srcA = Ag + (size_t)row0 * NC + kg + cc0 * 8;
            asm volatile("cp.async.cg.shared.global [%0], [%1], 16;" :: "r"(dA), "l"(srcA) : "memory");
#pragma unroll
            for (int h = 0; h < 2; h++) {
                const int row = row0 + h * 64;
                const uint32_t dB = sB0 + soB + (uint32_t)(row * SPA + cc0 * 8) * 2;
                const void* srcB = Bg + (size_t)(n0 + row) * NC + kg + cc0 * 8;
                asm volatile("cp.async.cg.shared.global [%0], [%1], 16;" :: "r"(dB), "l"(srcB) : "memory");
            }
            asm volatile("cp.async.commit_group;" ::: "memory");
            asm volatile("cp.async.wait_group 1;" ::: "memory");
        } else {
            asm volatile("cp.async.wait_group 0;" ::: "memory");
        }
        __syncthreads();

        const uint32_t stA = sA0 + (uint32_t)(s * 64 * SPA * 2);
        const uint32_t stB = sB0 + (uint32_t)(s * 128 * SPA * 2);
#pragma unroll
        for (int ks = 0; ks < 2; ks++) {
            uint32_t af[2][4];
#pragma unroll
            for (int mt = 0; mt < 2; mt++) {
                const uint32_t addr = stA + a_off + (uint32_t)(ks * 16) * 2 + (uint32_t)(mt * 16 * SPA) * 2;
                asm volatile("ldmatrix.sync.aligned.m8n8.x4.shared.b16 {%0,%1,%2,%3}, [%4];"
                             : "=r"(af[mt][0]), "=r"(af[mt][1]), "=r"(af[mt][2]), "=r"(af[mt][3])
                             : "r"(addr));
            }
            uint32_t bf[4][2];
#pragma unroll
            for (int nt = 0; nt < 4; nt++) {
                const uint32_t addr = stB + b_off + (uint32_t)(ks * 16) * 2 + (uint32_t)(nt * 8 * SPA) * 2;
                asm volatile("ldmatrix.sync.aligned.m8n8.x2.shared.b16 {%0,%1}, [%2];"
                             : "=r"(bf[nt][0]), "=r"(bf[nt][1]) : "r"(addr));
            }
#pragma unroll
            for (int mt = 0; mt < 2; mt++)
#pragma unroll
                for (int nt = 0; nt < 4; nt++) {
                    asm volatile(
                        "mma.sync.aligned.m16n8k16.row.col.f32.bf16.bf16.f32 "
                        "{%0,%1,%2,%3}, {%4,%5,%6,%7}, {%8,%9}, {%0,%1,%2,%3};"
                        : "+f"(acc[mt][nt][0]), "+f"(acc[mt][nt][1]),
                          "+f"(acc[mt][nt][2]), "+f"(acc[mt][nt][3])
                        : "r"(af[mt][0]), "r"(af[mt][1]), "r"(af[mt][2]), "r"(af[mt][3]),
                          "r"(bf[nt][0]), "r"(bf[nt][1]));
                }
        }
        __syncthreads();
    }

    const int erow = lane >> 2;
    const int ecol = (lane & 3) * 2;
#pragma unroll
    for (int mt = 0; mt < 2; mt++) {
        const int c = wm + mt * 16 + erow;
        const float b0 = bias[c], b1 = bias[c + 8];
#pragma unroll
        for (int nt = 0; nt < 4; nt++) {
            const int n = n0 + wn + nt * 8 + ecol;
            Out[(size_t)n * NCQ + c]           = __float2bfloat16(acc[mt][nt][0] + b0);
            Out[(size_t)(n + 1) * NCQ + c]     = __float2bfloat16(acc[mt][nt][1] + b0);
            Out[(size_t)n * NCQ + c + 8]       = __float2bfloat16(acc[mt][nt][2] + b1);
            Out[(size_t)(n + 1) * NCQ + c + 8] = __float2bfloat16(acc[mt][nt][3] + b1);
        }
    }
}

// =====================================================================
// V projection via HMMA: Vbf[c][n] bf16. grid (32, 4, NB)
// =====================================================================
__global__ __launch_bounds__(256, 2) void proj_v_mma(const float* __restrict__ bv)
{
    __shared__ __nv_bfloat16 smA[2][128 * SPA];
    __shared__ __nv_bfloat16 smB[2][128 * SPA];

    const int tid = threadIdx.x;
    const int wid = tid >> 5, lane = tid & 31;
    const int b = blockIdx.z;
    const int m0 = blockIdx.y * 128;
    const int n0 = blockIdx.x * 128;

    const __nv_bfloat16* __restrict__ Ag = g_Wv;
    const __nv_bfloat16* __restrict__ Bg = &g_Xt[0][b][0];

    const int wm = (wid & 1) * 64;
    const int wn = (wid >> 1) * 32;

    float acc[4][4][4];
#pragma unroll
    for (int i = 0; i < 4; i++)
#pragma unroll
        for (int j = 0; j < 4; j++)
#pragma unroll
            for (int q = 0; q < 4; q++) acc[i][j][q] = 0.f;

    const uint32_t sA0 = smem_u32(&smA[0][0]);
    const uint32_t sB0 = smem_u32(&smB[0][0]);
    const int row0 = tid >> 2, cc0 = tid & 3;

    const int la_row = wm + (lane & 15);
    const int la_col = (lane >> 4) << 3;
    const uint32_t a_off = (uint32_t)(la_row * SPA + la_col) * 2;
    const int lb_row = wn + (lane & 7);
    const int lb_col = ((lane >> 3) & 1) << 3;
    const uint32_t b_off = (uint32_t)(lb_row * SPA + lb_col) * 2;

    const int NT = NC / 32;

    {
#pragma unroll
        for (int h = 0; h < 2; h++) {
            const int row = row0 + h * 64;
            const uint32_t dA = sA0 + (uint32_t)(row * SPA + cc0 * 8) * 2;
            const uint32_t dB = sB0 + (uint32_t)(row * SPA + cc0 * 8) * 2;
            const void* srcA = Ag + (size_t)(m0 + row) * NC + cc0 * 8;
            const void* srcB = Bg + (size_t)(n0 + row) * NC + cc0 * 8;
            asm volatile("cp.async.cg.shared.global [%0], [%1], 16;" :: "r"(dA), "l"(srcA) : "memory");
            asm volatile("cp.async.cg.shared.global [%0], [%1], 16;" :: "r"(dB), "l"(srcB) : "memory");
        }
        asm volatile("cp.async.commit_group;" ::: "memory");
    }

    for (int kt = 0; kt < NT; ++kt) {
        const int s = kt & 1;
        if (kt + 1 < NT) {
            const int kg = (kt + 1) << 5;
            const uint32_t stoff = (uint32_t)((s ^ 1) * 128 * SPA * 2);
#pragma unroll
            for (int h = 0; h < 2; h++) {
                const int row = row0 + h * 64;
                const uint32_t dA = sA0 + stoff + (uint32_t)(row * SPA + cc0 * 8) * 2;
                const uint32_t dB = sB0 + stoff + (uint32_t)(row * SPA + cc0 * 8) * 2;
                const void* srcA = Ag + (size_t)(m0 + row) * NC + kg + cc0 * 8;
                const void* srcB = Bg + (size_t)(n0 + row) * NC + kg + cc0 * 8;
                asm volatile("cp.async.cg.shared.global [%0], [%1], 16;" :: "r"(dA), "l"(srcA) : "memory");
                asm volatile("cp.async.cg.shared.global [%0], [%1], 16;" :: "r"(dB), "l"(srcB) : "memory");
            }
            asm volatile("cp.async.commit_group;" ::: "memory");
            asm volatile("cp.async.wait_group 1;" ::: "memory");
        } else {
            asm volatile("cp.async.wait_group 0;" ::: "memory");
        }
        __syncthreads();

        const uint32_t stA = sA0 + (uint32_t)(s * 128 * SPA * 2);
        const uint32_t stB = sB0 + (uint32_t)(s * 128 * SPA * 2);
#pragma unroll
        for (int ks = 0; ks < 2; ks++) {
            uint32_t af[4][4];
#pragma unroll
            for (int mt = 0; mt < 4; mt++) {
                const uint32_t addr = stA + a_off + (uint32_t)(ks * 16) * 2 + (uint32_t)(mt * 16 * SPA) * 2;
                asm volatile("ldmatrix.sync.aligned.m8n8.x4.shared.b16 {%0,%1,%2,%3}, [%4];"
                             : "=r"(af[mt][0]), "=r"(af[mt][1]), "=r"(af[mt][2]), "=r"(af[mt][3])
                             : "r"(addr));
            }
            uint32_t bf[4][2];
#pragma unroll
            for (int nt = 0; nt < 4; nt++) {
                const uint32_t addr = stB + b_off + (uint32_t)(ks * 16) * 2 + (uint32_t)(nt * 8 * SPA) * 2;
                asm volatile("ldmatrix.sync.aligned.m8n8.x2.shared.b16 {%0,%1}, [%2];"
                             : "=r"(bf[nt][0]), "=r"(bf[nt][1]) : "r"(addr));
            }
#pragma unroll
            for (int mt = 0; mt < 4; mt++)
#pragma unroll
                for (int nt = 0; nt < 4; nt++) {
                    asm volatile(
                        "mma.sync.aligned.m16n8k16.row.col.f32.bf16.bf16.f32 "
                        "{%0,%1,%2,%3}, {%4,%5,%6,%7}, {%8,%9}, {%0,%1,%2,%3};"
                        : "+f"(acc[mt][nt][0]), "+f"(acc[mt][nt][1]),
                          "+f"(acc[mt][nt][2]), "+f"(acc[mt][nt][3])
                        : "r"(af[mt][0]), "r"(af[mt][1]), "r"(af[mt][2]), "r"(af[mt][3]),
                          "r"(bf[nt][0]), "r"(bf[nt][1]));
                }
        }
        __syncthreads();
    }

    __nv_bfloat16* __restrict__ V = &g_Vbf[b][0];
    const int erow = lane >> 2;
    const int ecol = (lane & 3) * 2;
#pragma unroll
    for (int mt = 0; mt < 4; mt++) {
        const int c = m0 + wm + mt * 16 + erow;
        const float b0 = bv[c], b1 = bv[c + 8];
#pragma unroll
        for (int nt = 0; nt < 4; nt++) {
            const int n = n0 + wn + nt * 8 + ecol;
            *(__nv_bfloat162*)(V + (size_t)c * NPIX + n) =
                __floats2bfloat162_rn(acc[mt][nt][0] + b0, acc[mt][nt][1] + b0);
            *(__nv_bfloat162*)(V + (size_t)(c + 8) * NPIX + n) =
                __floats2bfloat162_rn(acc[mt][nt][2] + b1, acc[mt][nt][3] + b1);
        }
    }
}

// =====================================================================
// Scores via HMMA + fused column-sum, SMEM-staged coalesced Et store.
// =====================================================================
#define SCB 72
#define STG 136   // staging stride (bf16): conflict-free bf162 writes

__global__ __launch_bounds__(256, 2) void scores_mma_kernel()
{
    __shared__ __nv_bfloat16 sm_buf[2 * 128 * SCB];   // A | B, reused as stage
    __shared__ float cs[128];

    const int tid = threadIdx.x;
    const int wid = tid >> 5, lane = tid & 31;
    const int zz = blockIdx.z;
    const int b = zz & 1, br = zz >> 1;
    const int m0 = blockIdx.y * 128;
    const int n0 = blockIdx.x * 128;

    const __nv_bfloat16* __restrict__ Ag = &g_Kt[br][b][0];
    const __nv_bfloat16* __restrict__ Bg = &g_Qt[b][0];

    const int wm = (wid & 1) * 64;
    const int wn = (wid >> 1) * 32;

    float acc[4][4][4];
#pragma unroll
    for (int i = 0; i < 4; i++)
#pragma unroll
        for (int j = 0; j < 4; j++)
#pragma unroll
            for (int q = 0; q < 4; q++) acc[i][j][q] = 0.f;

    const uint32_t sA0 = smem_u32(&sm_buf[0]);
    const uint32_t sB0 = smem_u32(&sm_buf[128 * SCB]);

#pragma unroll
    for (int c = 0; c < 4; c++) {
        const int idx = c * 256 + tid;
        const int row = idx >> 3, cc = idx & 7;
        const uint32_t dA = sA0 + (uint32_t)(row * SCB + cc * 8) * 2;
        const uint32_t dB = sB0 + (uint32_t)(row * SCB + cc * 8) * 2;
        const void* srcA = Ag + (size_t)(m0 + row) * NCQ + cc * 8;
        const void* srcB = Bg + (size_t)(n0 + row) * NCQ + cc * 8;
        asm volatile("cp.async.cg.shared.global [%0], [%1], 16;" :: "r"(dA), "l"(srcA) : "memory");
        asm volatile("cp.async.cg.shared.global [%0], [%1], 16;" :: "r"(dB), "l"(srcB) : "memory");
    }
    asm volatile("cp.async.commit_group;" ::: "memory");
    if (tid < 128) cs[tid] = 0.f;
    asm volatile("cp.async.wait_group 0;" ::: "memory");
    __syncthreads();

    const int la_row = wm + (lane & 15);
    const int la_col = (lane >> 4) << 3;
    const uint32_t a_off = sA0 + (uint32_t)(la_row * SCB + la_col) * 2;
    const int lb_row = wn + (lane & 7);
    const int lb_col = ((lane >> 3) & 1) << 3;
    const uint32_t b_off = sB0 + (uint32_t)(lb_row * SCB + lb_col) * 2;

#pragma unroll
    for (int ks = 0; ks < 4; ks++) {
        uint32_t af[4][4];
#pragma unroll
        for (int mt = 0; mt < 4; mt++) {
            const uint32_t addr = a_off + (uint32_t)(ks * 16) * 2 + (uint32_t)(mt * 16 * SCB) * 2;
            asm volatile("ldmatrix.sync.aligned.m8n8.x4.shared.b16 {%0,%1,%2,%3}, [%4];"
                         : "=r"(af[mt][0]), "=r"(af[mt][1]), "=r"(af[mt][2]), "=r"(af[mt][3])
                         : "r"(addr));
        }
        uint32_t bf[4][2];
#pragma unroll
        for (int nt = 0; nt < 4; nt++) {
            const uint32_t addr = b_off + (uint32_t)(ks * 16) * 2 + (uint32_t)(nt * 8 * SCB) * 2;
            asm volatile("ldmatrix.sync.aligned.m8n8.x2.shared.b16 {%0,%1}, [%2];"
                         : "=r"(bf[nt][0]), "=r"(bf[nt][1]) : "r"(addr));
        }
#pragma unroll
        for (int mt = 0; mt < 4; mt++)
#pragma unroll
            for (int nt = 0; nt < 4; nt++) {
                asm volatile(
                    "mma.sync.aligned.m16n8k16.row.col.f32.bf16.bf16.f32 "
                    "{%0,%1,%2,%3}, {%4,%5,%6,%7}, {%8,%9}, {%0,%1,%2,%3};"
                    : "+f"(acc[mt][nt][0]), "+f"(acc[mt][nt][1]),
                      "+f"(acc[mt][nt][2]), "+f"(acc[mt][nt][3])
                    : "r"(af[mt][0]), "r"(af[mt][1]), "r"(af[mt][2]), "r"(af[mt][3]),
                      "r"(bf[nt][0]), "r"(bf[nt][1]));
            }
    }
    __syncthreads();   // all ldsm done before stage overwrite

    // exp + stage into SMEM [m_local][n_local], accumulate column sums
    __nv_bfloat16* stage = &sm_buf[0];
    const int erow = lane >> 2;
    const int ecol = (lane & 3) * 2;
#pragma unroll
    for (int nt = 0; nt < 4; nt++) {
        const int cl = wn + nt * 8 + ecol;
        float s0 = 0.f, s1 = 0.f;
#pragma unroll
        for (int mt = 0; mt < 4; mt++) {
            const int rl = wm + mt * 16 + erow;
            float e0 = __expf(acc[mt][nt][0]);
            float e1 = __expf(acc[mt][nt][1]);
            float e2 = __expf(acc[mt][nt][2]);
            float e3 = __expf(acc[mt][nt][3]);
            *(__nv_bfloat162*)(stage + rl * STG + cl)       = __floats2bfloat162_rn(e0, e1);
            *(__nv_bfloat162*)(stage + (rl + 8) * STG + cl) = __floats2bfloat162_rn(e2, e3);
            s0 += e0 + e2;
            s1 += e1 + e3;
        }
        atomicAdd(&cs[cl], s0);
        atomicAdd(&cs[cl + 1], s1);
    }
    __syncthreads();

    // coalesced store: 128 rows x 256B
    __nv_bfloat16* __restrict__ E = &g_Et[zz][0];
#pragma unroll
    for (int c = 0; c < 8; c++) {
        const int id = c * 256 + tid;
        const int row = id >> 4, c16 = id & 15;
        *(uint4*)(E + (size_t)(m0 + row) * NPIX + n0 + c16 * 8) =
            *(const uint4*)(stage + row * STG + c16 * 8);
    }
    if (tid < 128) atomicAdd(&g_Zsum[zz][n0 + tid], cs[tid]);
}

// ===================== invert Z =====================
__global__ __launch_bounds__(1024) void invertZ_kernel()
{
    const int zz = blockIdx.x;
#pragma unroll
    for (int k = 0; k < 4; k++) {
        const int i = threadIdx.x + k * 1024;
        g_invZ[zz][i] = 1.0f / g_Zsum[zz][i];
    }
}

// ===================== A = bf16(V * invZ), from bf16 V =====================
__global__ __launch_bounds__(256) void convertA_kernel()
{
    const int b = blockIdx.z, c = blockIdx.y;
    const int base = blockIdx.x * 2048 + threadIdx.x * 8;
    const int br = base >> 12;
    const int i = base & 4095;
    const __nv_bfloat16* Vp = &g_Vbf[b][0] + (size_t)c * NPIX + i;
    const float* iz = &g_invZ[br * 2 + b][0] + i;
    union { __nv_bfloat162 h2[4]; uint4 v; } vi;
    vi.v = *(const uint4*)Vp;
    float4 z0 = *(const float4*)iz, z1 = *(const float4*)(iz + 4);
    union { __nv_bfloat162 h2[4]; uint4 v; } t;
    t.h2[0] = __floats2bfloat162_rn(__bfloat162float(vi.h2[0].x) * z0.x, __bfloat162float(vi.h2[0].y) * z0.y);
    t.h2[1] = __floats2bfloat162_rn(__bfloat162float(vi.h2[1].x) * z0.z, __bfloat162float(vi.h2[1].y) * z0.w);
    t.h2[2] = __floats2bfloat162_rn(__bfloat162float(vi.h2[2].x) * z1.x, __bfloat162float(vi.h2[2].y) * z1.y);
    t.h2[3] = __floats2bfloat162_rn(__bfloat162float(vi.h2[3].x) * z1.z, __bfloat162float(vi.h2[3].y) * z1.w);
    *(uint4*)(&g_Abf[b][0] + (size_t)c * KTOT + base) = t.v;
}

// =====================================================================
// Aggregation GEMM v1 (HMMA, proven) + x4 B-ldsm:
// attT[n][c] via A=Abf, B=Et. Block 128x128, BK=32, warp 64x32.
// grid (32, 4, NB), 256 threads, 40KB static SMEM.
// =====================================================================
#define SA 40

__global__ __launch_bounds__(256, 2) void attn_mma_kernel()
{
    __shared__ __nv_bfloat16 smA[2][128 * SA];
    __shared__ __nv_bfloat16 smB[2][128 * SA];

    const int tid = threadIdx.x;
    const int wid = tid >> 5, lane = tid & 31;
    const int b = blockIdx.z;
    const int m0 = blockIdx.y * 128;
    const int n0 = blockIdx.x * 128;

    const __nv_bfloat16* __restrict__ Ag = &g_Abf[b][0];

    const int wm = (wid & 1) * 64;
    const int wn = (wid >> 1) * 32;

    float acc[4][4][4];
#pragma unroll
    for (int i = 0; i < 4; i++)
#pragma unroll
        for (int j = 0; j < 4; j++)
#pragma unroll
            for (int q = 0; q < 4; q++) acc[i][j][q] = 0.f;

    const uint32_t sA0 = smem_u32(&smA[0][0]);
    const uint32_t sB0 = smem_u32(&smB[0][0]);

    const int row0 = tid >> 2;
    const int cc0  = tid & 3;

    const int la_row = wm + (lane & 15);
    const int la_col = (lane >> 4) << 3;
    const uint32_t a_off = (uint32_t)(la_row * SA + la_col) * 2;
    // x4 B-ldsm mapping (HW-validated in R8): 4 matrices = 2 n-tiles x 2 k-halves
    const int lbx_row = (lane & 7) + ((lane >> 4) << 3);
    const int lbx_col = ((lane >> 3) & 1) << 3;
    const uint32_t b_off = (uint32_t)((wn + lbx_row) * SA + lbx_col) * 2;

    const int NT = KTOT / 32;  // 384

    {
        const __nv_bfloat16* Bg = &g_Et[b][0];
#pragma unroll
        for (int h = 0; h < 2; h++) {
            const int row = row0 + h * 64;
            const uint32_t dA = sA0 + (uint32_t)(row * SA + cc0 * 8) * 2;
            const uint32_t dB = sB0 + (uint32_t)(row * SA + cc0 * 8) * 2;
            const void* srcA = Ag + (size_t)(m0 + row) * KTOT + cc0 * 8;
            const void* srcB = Bg + (size_t)(n0 + row) * NPIX + cc0 * 8;
            asm volatile("cp.async.cg.shared.global [%0], [%1], 16;" :: "r"(dA), "l"(srcA) : "memory");
            asm volatile("cp.async.cg.shared.global [%0], [%1], 16;" :: "r"(dB), "l"(srcB) : "memory");
        }
        asm volatile("cp.async.commit_group;" ::: "memory");
    }

    for (int kt = 0; kt < NT; ++kt) {
        const int s = kt & 1;
        if (kt + 1 < NT) {
            const int kg = (kt + 1) << 5;
            const int br = kg >> 12;
            const int kloc = kg & 4095;
            const __nv_bfloat16* __restrict__ Bg = &g_Et[br * 2 + b][0];
            const uint32_t stoff = (uint32_t)((s ^ 1) * 128 * SA * 2);
#pragma unroll
            for (int h = 0; h < 2; h++) {
                const int row = row0 + h * 64;
                const uint32_t dA = sA0 + stoff + (uint32_t)(row * SA + cc0 * 8) * 2;
                const uint32_t dB = sB0 + stoff + (uint32_t)(row * SA + cc0 * 8) * 2;
                const void* srcA = Ag + (size_t)(m0 + row) * KTOT + kg + cc0 * 8;
                const void* srcB = Bg + (size_t)(n0 + row) * NPIX + kloc + cc0 * 8;
                asm volatile("cp.async.cg.shared.global [%0], [%1], 16;" :: "r"(dA), "l"(srcA) : "memory");
                asm volatile("cp.async.cg.shared.global [%0], [%1], 16;" :: "r"(dB), "l"(srcB) : "memory");
            }
            asm volatile("cp.async.commit_group;" ::: "memory");
            asm volatile("cp.async.wait_group 1;" ::: "memory");
        } else {
            asm volatile("cp.async.wait_group 0;" ::: "memory");
        }
        __syncthreads();

        const uint32_t stA = sA0 + (uint32_t)(s * 128 * SA * 2);
        const uint32_t stB = sB0 + (uint32_t)(s * 128 * SA * 2);

#pragma unroll
        for (int ks = 0; ks < 2; ks++) {
            uint32_t af[4][4];
#pragma unroll
            for (int mt = 0; mt < 4; mt++) {
                const uint32_t addr = stA + a_off + (uint32_t)(ks * 16) * 2 + (uint32_t)(mt * 16 * SA) * 2;
                asm volatile("ldmatrix.sync.aligned.m8n8.x4.shared.b16 {%0,%1,%2,%3}, [%4];"
                             : "=r"(af[mt][0]), "=r"(af[mt][1]), "=r"(af[mt][2]), "=r"(af[mt][3])
                             : "r"(addr));
            }
            uint32_t bf[4][2];
#pragma unroll
            for (int ntp = 0; ntp < 2; ntp++) {
                const uint32_t addr = stB + b_off + (uint32_t)(ks * 16) * 2 + (uint32_t)(ntp * 16 * SA) * 2;
                asm volatile("ldmatrix.sync.aligned.m8n8.x4.shared.b16 {%0,%1,%2,%3}, [%4];"
                             : "=r"(bf[ntp * 2][0]), "=r"(bf[ntp * 2][1]),
                               "=r"(bf[ntp * 2 + 1][0]), "=r"(bf[ntp * 2 + 1][1])
                             : "r"(addr));
            }
#pragma unroll
            for (int mt = 0; mt < 4; mt++)
#pragma unroll
                for (int nt = 0; nt < 4; nt++) {
                    asm volatile(
                        "mma.sync.aligned.m16n8k16.row.col.f32.bf16.bf16.f32 "
                        "{%0,%1,%2,%3}, {%4,%5,%6,%7}, {%8,%9}, {%0,%1,%2,%3};"
                        : "+f"(acc[mt][nt][0]), "+f"(acc[mt][nt][1]),
                          "+f"(acc[mt][nt][2]), "+f"(acc[mt][nt][3])
                        : "r"(af[mt][0]), "r"(af[mt][1]), "r"(af[mt][2]), "r"(af[mt][3]),
                          "r"(bf[nt][0]), "r"(bf[nt][1]));
                }
        }
        __syncthreads();
    }

    __nv_bfloat16* __restrict__ at = &g_attT[b][0];
    const int erow = lane >> 2;
    const int ecol = (lane & 3) * 2;
#pragma unroll
    for (int mt = 0; mt < 4; mt++) {
#pragma unroll
        for (int nt = 0; nt < 4; nt++) {
            const int m = m0 + wm + mt * 16 + erow;
            const int n = n0 + wn + nt * 8 + ecol;
            at[(size_t)n * NC + m]           = __float2bfloat16(acc[mt][nt][0]);
            at[(size_t)(n + 1) * NC + m]     = __float2bfloat16(acc[mt][nt][1]);
            at[(size_t)n * NC + m + 8]       = __float2bfloat16(acc[mt][nt][2]);
            at[(size_t)(n + 1) * NC + m + 8] = __float2bfloat16(acc[mt][nt][3]);
        }
    }
}

// =====================================================================
// Final via HMMA: out[c][n] = x + gamma*(Wl@att + bl). grid (32, 4, NB)
// =====================================================================
__global__ __launch_bounds__(256, 2) void final_mma(
    const float* __restrict__ bl, const float* __restrict__ xin,
    const float* __restrict__ gamma, float* __restrict__ out)
{
    __shared__ __nv_bfloat16 smA[2][128 * SPA];
    __shared__ __nv_bfloat16 smB[2][128 * SPA];

    const int tid = threadIdx.x;
    const int wid = tid >> 5, lane = tid & 31;
    const int b = blockIdx.z;
    const int m0 = blockIdx.y * 128;
    const int n0 = blockIdx.x * 128;

    const __nv_bfloat16* __restrict__ Ag = g_Wl;
    const __nv_bfloat16* __restrict__ Bg = &g_attT[b][0];

    const int wm = (wid & 1) * 64;
    const int wn = (wid >> 1) * 32;

    float acc[4][4][4];
#pragma unroll
    for (int i = 0; i < 4; i++)
#pragma unroll
        for (int j = 0; j < 4; j++)
#pragma unroll
            for (int q = 0; q < 4; q++) acc[i][j][q] = 0.f;

    const uint32_t sA0 = smem_u32(&smA[0][0]);
    const uint32_t sB0 = smem_u32(&smB[0][0]);
    const int row0 = tid >> 2, cc0 = tid & 3;

    const int la_row = wm + (lane & 15);
    const int la_col = (lane >> 4) << 3;
    const uint32_t a_off = (uint32_t)(la_row * SPA + la_col) * 2;
    const int lb_row = wn + (lane & 7);
    const int lb_col = ((lane >> 3) & 1) << 3;
    const uint32_t b_off = (uint32_t)(lb_row * SPA + lb_col) * 2;

    const int NT = NC / 32;

    {
#pragma unroll
        for (int h = 0; h < 2; h++) {
            const int row = row0 + h * 64;
            const uint32_t dA = sA0 + (uint32_t)(row * SPA + cc0 * 8) * 2;
            const uint32_t dB = sB0 + (uint32_t)(row * SPA + cc0 * 8) * 2;
            const void* srcA = Ag + (size_t)(m0 + row) * NC + cc0 * 8;
            const void* srcB = Bg + (size_t)(n0 + row) * NC + cc0 * 8;
            asm volatile("cp.async.cg.shared.global [%0], [%1], 16;" :: "r"(dA), "l"(srcA) : "memory");
            asm volatile("cp.async.cg.shared.global [%0], [%1], 16;" :: "r"(dB), "l"(srcB) : "memory");
        }
        asm volatile("cp.async.commit_group;" ::: "memory");
    }

    for (int kt = 0; kt < NT; ++kt) {
        const int s = kt & 1;
        if (kt + 1 < NT) {
            const int kg = (kt + 1) << 5;
            const uint32_t stoff = (uint32_t)((s ^ 1) * 128 * SPA * 2);
#pragma unroll
            for (int h = 0; h < 2; h++) {
                const int row = row0 + h * 64;
                const uint32_t dA = sA0 + stoff + (uint32_t)(row * SPA + cc0 * 8) * 2;
                const uint32_t dB = sB0 + stoff + (uint32_t)(row * SPA + cc0 * 8) * 2;
                const void* srcA = Ag + (size_t)(m0 + row) * NC + kg + cc0 * 8;
                const void* srcB = Bg + (size_t)(n0 + row) * NC + kg + cc0 * 8;
                asm volatile("cp.async.cg.shared.global [%0], [%1], 16;" :: "r"(dA), "l"(srcA) : "memory");
                asm volatile("cp.async.cg.shared.global [%0], [%1], 16;" :: "r"(dB), "l"(srcB) : "memory");
            }
            asm volatile("cp.async.commit_group;" ::: "memory");
            asm volatile("cp.async.wait_group 1;" ::: "memory");
        } else {
            asm volatile("cp.async.wait_group 0;" ::: "memory");
        }
        __syncthreads();

        const uint32_t stA = sA0 + (uint32_t)(s * 128 * SPA * 2);
        const uint32_t stB = sB0 + (uint32_t)(s * 128 * SPA * 2);
#pragma unroll
        for (int ks = 0; ks < 2; ks++) {
            uint32_t af[4][4];
#pragma unroll
            for (int mt = 0; mt < 4; mt++) {
                const uint32_t addr = stA + a_off + (uint32_t)(ks * 16) * 2 + (uint32_t)(mt * 16 * SPA) * 2;
                asm volatile("ldmatrix.sync.aligned.m8n8.x4.shared.b16 {%0,%1,%2,%3}, [%4];"
                             : "=r"(af[mt][0]), "=r"(af[mt][1]), "=r"(af[mt][2]), "=r"(af[mt][3])
                             : "r"(addr));
            }
            uint32_t bf[4][2];
#pragma unroll
            for (int nt = 0; nt < 4; nt++) {
                const uint32_t addr = stB + b_off + (uint32_t)(ks * 16) * 2 + (uint32_t)(nt * 8 * SPA) * 2;
                asm volatile("ldmatrix.sync.aligned.m8n8.x2.shared.b16 {%0,%1}, [%2];"
                             : "=r"(bf[nt][0]), "=r"(bf[nt][1]) : "r"(addr));
            }
#pragma unroll
            for (int mt = 0; mt < 4; mt++)
#pragma unroll
                for (int nt = 0; nt < 4; nt++) {
                    asm volatile(
                        "mma.sync.aligned.m16n8k16.row.col.f32.bf16.bf16.f32 "
                        "{%0,%1,%2,%3}, {%4,%5,%6,%7}, {%8,%9}, {%0,%1,%2,%3};"
                        : "+f"(acc[mt][nt][0]), "+f"(acc[mt][nt][1]),
                          "+f"(acc[mt][nt][2]), "+f"(acc[mt][nt][3])
                        : "r"(af[mt][0]), "r"(af[mt][1]), "r"(af[mt][2]), "r"(af[mt][3]),
                          "r"(bf[nt][0]), "r"(bf[nt][1]));
                }
        }
        __syncthreads();
    }

    const float g = gamma[0];
    const int erow = lane >> 2;
    const int ecol = (lane & 3) * 2;
#pragma unroll
    for (int mt = 0; mt < 4; mt++) {
        const int c = m0 + wm + mt * 16 + erow;
        const float b0 = bl[c], b1 = bl[c + 8];
#pragma unroll
        for (int nt = 0; nt < 4; nt++) {
            const int n = n0 + wn + nt * 8 + ecol;
            const size_t base0 = (size_t)b * NC * NPIX + (size_t)c * NPIX + n;
            const size_t base1 = (size_t)b * NC * NPIX + (size_t)(c + 8) * NPIX + n;
            float2 x0 = *(const float2*)(xin + base0);
            float2 x1 = *(const float2*)(xin + base1);
            *(float2*)(out + base0) = make_float2(x0.x + g * (acc[mt][nt][0] + b0),
                                                  x0.y + g * (acc[mt][nt][1] + b0));
            *(float2*)(out + base1) = make_float2(x1.x + g * (acc[mt][nt][2] + b1),
                                                  x1.y + g * (acc[mt][nt][3] + b1));
        }
    }
}

// =====================================================================
extern "C" void kernel_launch(void* const* d_in, const int* in_sizes, int n_in,
                              void* d_out, int out_size)
{
    const float* x   = (const float*)d_in[0];
    const float* y   = (const float*)d_in[1];
    const float* zz  = (const float*)d_in[2];
    const float* Wq  = (const float*)d_in[3];
    const float* bq  = (const float*)d_in[4];
    const float* Wk1 = (const float*)d_in[5];
    const float* bk1 = (const float*)d_in[6];
    const float* Wk2 = (const float*)d_in[7];
    const float* bk2 = (const float*)d_in[8];
    const float* Wk3 = (const float*)d_in[9];
    const float* bk3 = (const float*)d_in[10];
    const float* Wv  = (const float*)d_in[11];
    const float* bv  = (const float*)d_in[12];
    const float* Wl  = (const float*)d_in[13];
    const float* bl  = (const float*)d_in[14];
    const float* gm  = (const float*)d_in[15];
    float* out = (float*)d_out;

    dim3 blk(256);
    convertW_kernel<<<2560, blk>>>(Wq, Wk1, Wk2, Wk3, Wv, Wl);
    transposeX_kernel<<<dim3(128, 16, 6), dim3(32, 8)>>>(x, y, zz);
    proj_qk_mma<<<dim3(32, 4, NB), blk>>>(bq, bk1, bk2, bk3);
    proj_v_mma <<<dim3(32, 4, NB), blk>>>(bv);
    scores_mma_kernel<<<dim3(32, 32, 6), blk>>>();
    invertZ_kernel<<<6, 1024>>>();
    convertA_kernel<<<dim3(6, 512, NB), blk>>>();
    attn_mma_kernel<<<dim3(32, 4, NB), blk>>>();
    final_mma<<<dim3(32, 4, NB), blk>>>(bl, x, gm, out);
}